// round 5
// baseline (speedup 1.0000x reference)
#include <cuda_runtime.h>
#include <cuda_bf16.h>
#include <math.h>
#include <stdint.h>

#define BATCH 2
#define SEQL  2048
#define DMODEL 768
#define NH    12
#define HD    64
#define KSEL  46
#define NKV   1536
#define NROWS (BATCH*SEQL)
#define WQKV_COLS 2304
#define NQ    (BATCH*KSEL)
#define NQP   96
#define CH    64
#define NCH   (SEQL/CH)

// -------- scratch --------
__device__ float g_p1[NROWS];
__device__ int   g_idx[NQ];
__device__ float g_kv[(size_t)NROWS * NKV];
__device__ float g_q[NQP*DMODEL];
__device__ float g_ctx[NQP*DMODEL];
__device__ float g_pm[BATCH*NH*NCH*48];
__device__ float g_pl[BATCH*NH*NCH*48];
__device__ float g_po[(size_t)BATCH*NH*NCH*48*HD];
__device__ __nv_bfloat16 g_xb[(size_t)NROWS * DMODEL];   // X bf16 [row][k]
__device__ __nv_bfloat16 g_wt[(size_t)NKV * DMODEL];     // W_kv bf16 [n][k]

__device__ __forceinline__ uint32_t smem_u32(const void* p) {
    uint32_t a;
    asm("{ .reg .u64 t; cvta.to.shared.u64 t, %1; cvt.u32.u64 %0, t; }" : "=r"(a) : "l"(p));
    return a;
}
__device__ __forceinline__ void ldm_x4(uint32_t* r, uint32_t addr) {
    asm volatile("ldmatrix.sync.aligned.m8n8.x4.shared.b16 {%0,%1,%2,%3}, [%4];"
        : "=r"(r[0]), "=r"(r[1]), "=r"(r[2]), "=r"(r[3]) : "r"(addr));
}
__device__ __forceinline__ void mma16816(float* c, const uint32_t* a, uint32_t b0, uint32_t b1) {
    asm volatile(
        "mma.sync.aligned.m16n8k16.row.col.f32.bf16.bf16.f32 "
        "{%0,%1,%2,%3}, {%4,%5,%6,%7}, {%8,%9}, {%0,%1,%2,%3};"
        : "+f"(c[0]), "+f"(c[1]), "+f"(c[2]), "+f"(c[3])
        : "r"(a[0]), "r"(a[1]), "r"(a[2]), "r"(a[3]), "r"(b0), "r"(b1));
}

// ============================================================================
// sel prob + y=x copy + x->bf16 convert (fused)
// ============================================================================
__global__ void sel_copy_kernel(const float* __restrict__ x,
                                const float* __restrict__ sel_w,
                                const float* __restrict__ sel_b,
                                const float* __restrict__ temp,
                                float* __restrict__ y) {
    int r = blockIdx.x;
    const float* xr = x + (size_t)r * DMODEL;
    float* yr = y + (size_t)r * DMODEL;
    __nv_bfloat16* xb = g_xb + (size_t)r * DMODEL;
    int tid = threadIdx.x;
    float p0 = 0.f, p1 = 0.f;
    #pragma unroll
    for (int j = tid; j < DMODEL; j += 256) {
        float v = xr[j];
        yr[j] = v;
        xb[j] = __float2bfloat16(v);
        float2 w = *(const float2*)&sel_w[2*j];
        p0 = fmaf(v, w.x, p0);
        p1 = fmaf(v, w.y, p1);
    }
    #pragma unroll
    for (int off = 16; off; off >>= 1) {
        p0 += __shfl_down_sync(0xffffffffu, p0, off);
        p1 += __shfl_down_sync(0xffffffffu, p1, off);
    }
    __shared__ float s0[8], s1[8];
    int w = tid >> 5;
    if ((tid & 31) == 0) { s0[w] = p0; s1[w] = p1; }
    __syncthreads();
    if (tid == 0) {
        float a0 = 0.f, a1 = 0.f;
        #pragma unroll
        for (int i = 0; i < 8; i++) { a0 += s0[i]; a1 += s1[i]; }
        a0 += sel_b[0]; a1 += sel_b[1];
        float d = (a1 - a0) / temp[0];
        g_p1[r] = 1.0f / (1.0f + expf(-d));
    }
}

// ============================================================================
// W_kv (cols 768:2304) -> g_wt[n][k] bf16 (transpose)
// ============================================================================
__global__ void w_transpose_kernel(const float* __restrict__ W) {
    __shared__ float t[32][33];
    int n0 = blockIdx.x * 32;
    int k0 = blockIdx.y * 32;
    int tx = threadIdx.x, ty = threadIdx.y;
    #pragma unroll
    for (int i = 0; i < 4; i++)
        t[ty + 8*i][tx] = W[(size_t)(k0 + ty + 8*i) * WQKV_COLS + 768 + n0 + tx];
    __syncthreads();
    #pragma unroll
    for (int i = 0; i < 4; i++)
        g_wt[(size_t)(n0 + ty + 8*i) * DMODEL + k0 + tx] = __float2bfloat16(t[tx][ty + 8*i]);
}

// ============================================================================
// KV GEMM: mma.sync + ldmatrix. C[4096x1536] = Xb @ Wt^T (+bias).
// CTA 128(M)x128(N), K-chunk 32, 8 warps (2M x 4N), warp tile 64x32.
// ============================================================================
#define AST 40   // smem row stride (bf16) — conflict-free for ldmatrix phases

__global__ void __launch_bounds__(256) kv_mma_kernel(const float* __restrict__ bias) {
    __shared__ __nv_bfloat16 sA[128*AST];   // 10 KB
    __shared__ __nv_bfloat16 sB[128*AST];   // 10 KB
    int tid = threadIdx.x;
    int wid = tid >> 5, lane = tid & 31;
    int wm = wid & 1, wn = wid >> 1;        // 2M x 4N
    int g = lane >> 2, tg = lane & 3;
    int row0 = blockIdx.y * 128;
    int col0 = blockIdx.x * 128;

    // loader coords: 2 uint4 per thread per tile
    int lr0 = tid >> 2, lu = tid & 3;       // rows tid/4 and tid/4+64
    const __nv_bfloat16* gA0 = g_xb + (size_t)(row0 + lr0) * DMODEL + lu * 8;
    const __nv_bfloat16* gA1 = g_xb + (size_t)(row0 + lr0 + 64) * DMODEL + lu * 8;
    const __nv_bfloat16* gB0 = g_wt + (size_t)(col0 + lr0) * DMODEL + lu * 8;
    const __nv_bfloat16* gB1 = g_wt + (size_t)(col0 + lr0 + 64) * DMODEL + lu * 8;
    __nv_bfloat16* stA0 = &sA[lr0 * AST + lu * 8];
    __nv_bfloat16* stA1 = &sA[(lr0 + 64) * AST + lu * 8];
    __nv_bfloat16* stB0 = &sB[lr0 * AST + lu * 8];
    __nv_bfloat16* stB1 = &sB[(lr0 + 64) * AST + lu * 8];

    // ldmatrix lane addressing
    int lrow = lane & 15, lsel = (lane >> 4) * 8;
    uint32_t aBase = smem_u32(sA) + (uint32_t)(((wm*64 + lrow) * AST + lsel) * 2);
    uint32_t bBase = smem_u32(sB) + (uint32_t)(((wn*32 + lrow) * AST + lsel) * 2);

    float c[4][4][4];
    #pragma unroll
    for (int mi = 0; mi < 4; mi++)
        #pragma unroll
        for (int ni = 0; ni < 4; ni++)
            #pragma unroll
            for (int j = 0; j < 4; j++) c[mi][ni][j] = 0.f;

    uint4 pA0 = *(const uint4*)gA0, pA1 = *(const uint4*)gA1;
    uint4 pB0 = *(const uint4*)gB0, pB1 = *(const uint4*)gB1;

    for (int kc = 0; kc < 24; kc++) {
        *(uint4*)stA0 = pA0; *(uint4*)stA1 = pA1;
        *(uint4*)stB0 = pB0; *(uint4*)stB1 = pB1;
        __syncthreads();
        if (kc < 23) {
            int k0 = (kc + 1) * 32;
            pA0 = *(const uint4*)(gA0 + k0); pA1 = *(const uint4*)(gA1 + k0);
            pB0 = *(const uint4*)(gB0 + k0); pB1 = *(const uint4*)(gB1 + k0);
        }
        #pragma unroll
        for (int ks = 0; ks < 2; ks++) {
            uint32_t A[4][4], Bf[2][4];
            #pragma unroll
            for (int mi = 0; mi < 4; mi++)
                ldm_x4(A[mi], aBase + (uint32_t)((mi*16*AST + ks*16) * 2));
            #pragma unroll
            for (int bi = 0; bi < 2; bi++)
                ldm_x4(Bf[bi], bBase + (uint32_t)((bi*16*AST + ks*16) * 2));
            #pragma unroll
            for (int mi = 0; mi < 4; mi++) {
                mma16816(c[mi][0], A[mi], Bf[0][0], Bf[0][2]);
                mma16816(c[mi][1], A[mi], Bf[0][1], Bf[0][3]);
                mma16816(c[mi][2], A[mi], Bf[1][0], Bf[1][2]);
                mma16816(c[mi][3], A[mi], Bf[1][1], Bf[1][3]);
            }
        }
        __syncthreads();
    }

    #pragma unroll
    for (int mi = 0; mi < 4; mi++) {
        int row = row0 + wm * 64 + mi * 16;
        #pragma unroll
        for (int ni = 0; ni < 4; ni++) {
            int col = col0 + wn * 32 + ni * 8 + 2 * tg;
            float2 bb = *(const float2*)&bias[768 + col];
            float2 r0, r1;
            r0.x = c[mi][ni][0] + bb.x; r0.y = c[mi][ni][1] + bb.y;
            r1.x = c[mi][ni][2] + bb.x; r1.y = c[mi][ni][3] + bb.y;
            *(float2*)&g_kv[(size_t)(row + g) * NKV + col] = r0;
            *(float2*)&g_kv[(size_t)(row + g + 8) * NKV + col] = r1;
        }
    }
}

// ============================================================================
// top-KSEL per batch, 256 threads
// ============================================================================
__global__ void topk_kernel() {
    int b = blockIdx.x;
    __shared__ float vals[SEQL];
    __shared__ float rv[8];
    __shared__ int   ri[8];
    int tid = threadIdx.x;
    for (int j = tid; j < SEQL; j += 256) vals[j] = g_p1[b*SEQL + j];
    __syncthreads();
    for (int k = 0; k < KSEL; k++) {
        float bv = -1e30f; int bi = 1 << 30;
        #pragma unroll
        for (int l = 0; l < 8; l++) {
            int j = tid + l * 256;
            float v = vals[j];
            if (v > bv) { bv = v; bi = j; }
        }
        #pragma unroll
        for (int off = 16; off; off >>= 1) {
            float ov = __shfl_xor_sync(0xffffffffu, bv, off);
            int   oi = __shfl_xor_sync(0xffffffffu, bi, off);
            if (ov > bv || (ov == bv && oi < bi)) { bv = ov; bi = oi; }
        }
        if ((tid & 31) == 0) { rv[tid >> 5] = bv; ri[tid >> 5] = bi; }
        __syncthreads();
        if (tid == 0) {
            float fv = rv[0]; int fi = ri[0];
            #pragma unroll
            for (int i = 1; i < 8; i++)
                if (rv[i] > fv || (rv[i] == fv && ri[i] < fi)) { fv = rv[i]; fi = ri[i]; }
            g_idx[b*KSEL + k] = fi;
            vals[fi] = -2e30f;
        }
        __syncthreads();
    }
}

// ============================================================================
// Q projection: gathered rows directly from x, full-K loop (no atomics).
// grid (12 coltiles, 2 rowtiles of 48)
// ============================================================================
__global__ void __launch_bounds__(256) qproj_kernel(const float* __restrict__ x,
                                                    const float* __restrict__ W,
                                                    const float* __restrict__ bias) {
    __shared__ float As[64*48];
    __shared__ float Bs[64*64];
    __shared__ int rowsrc[48];
    int tid = threadIdx.x;
    int tx = tid & 15, ty = tid >> 4;
    int cb = blockIdx.x * 64;
    int rt = blockIdx.y;
    if (tid < 48) {
        int r = rt*48 + tid;
        rowsrc[tid] = (r < NQ) ? ((r / KSEL) * SEQL + g_idx[r]) : -1;
    }
    __syncthreads();

    float acc[3][4];
    #pragma unroll
    for (int i = 0; i < 3; i++)
        #pragma unroll
        for (int j = 0; j < 4; j++) acc[i][j] = 0.f;

    for (int kb = 0; kb < DMODEL; kb += 64) {
        #pragma unroll
        for (int l = 0; l < 3; l++) {
            int fid = tid + l*256;
            int row = fid >> 4;
            int kc  = (fid & 15) << 2;
            int src = rowsrc[row];
            float4 v = make_float4(0.f, 0.f, 0.f, 0.f);
            if (src >= 0) v = *(const float4*)&x[(size_t)src*DMODEL + kb + kc];
            As[(kc+0)*48 + row] = v.x; As[(kc+1)*48 + row] = v.y;
            As[(kc+2)*48 + row] = v.z; As[(kc+3)*48 + row] = v.w;
        }
        #pragma unroll
        for (int l = 0; l < 4; l++) {
            int fid = tid + l*256;
            int kr = fid >> 4;
            int c4 = (fid & 15) << 2;
            *(float4*)&Bs[kr*64 + c4] = *(const float4*)&W[(size_t)(kb + kr)*WQKV_COLS + cb + c4];
        }
        __syncthreads();
        #pragma unroll 8
        for (int k = 0; k < 64; k++) {
            float4 bv = *(const float4*)&Bs[k*64 + tx*4];
            #pragma unroll
            for (int i = 0; i < 3; i++) {
                float a = As[k*48 + ty*3 + i];
                acc[i][0] = fmaf(a, bv.x, acc[i][0]);
                acc[i][1] = fmaf(a, bv.y, acc[i][1]);
                acc[i][2] = fmaf(a, bv.z, acc[i][2]);
                acc[i][3] = fmaf(a, bv.w, acc[i][3]);
            }
        }
        __syncthreads();
    }
    #pragma unroll
    for (int i = 0; i < 3; i++) {
        int row = rt*48 + ty*3 + i;
        if (row < NQ) {
            #pragma unroll
            for (int j = 0; j < 4; j++) {
                int col = cb + tx*4 + j;
                g_q[(size_t)row*DMODEL + col] = acc[i][j] + bias[col];
            }
        }
    }
}

// ============================================================================
// flash-decode attention chunk (fp32)
// ============================================================================
__global__ void __launch_bounds__(256) attn_chunk_kernel() {
    int c  = blockIdx.x;
    int h  = blockIdx.y;
    int b  = blockIdx.z;
    int c0 = c * CH;
    int tid = threadIdx.x;
    int tx = tid & 15, ty = tid >> 4;

    __shared__ float qs[48*HD];
    __shared__ float kv_s[CH*HD];
    __shared__ float S[48*66];
    __shared__ int   ts[48];

    if (tid < 48) ts[tid] = (tid < KSEL) ? g_idx[b*KSEL + tid] : -1;
    for (int idx = tid; idx < 48*HD; idx += 256) {
        int q = idx >> 6, d = idx & 63;
        qs[idx] = (q < KSEL) ? g_q[(size_t)(b*KSEL + q)*DMODEL + h*HD + d] * 0.125f : 0.f;
    }
    const float* kvb = g_kv + (size_t)b * SEQL * NKV;
    #pragma unroll
    for (int l = 0; l < 4; l++) {
        int fid = tid + l*256;
        int key = fid >> 4;
        int dq  = (fid & 15) << 2;
        float4 v = *(const float4*)&kvb[(size_t)(c0 + key)*NKV + h*HD + dq];
        kv_s[(dq+0)*CH + key] = v.x; kv_s[(dq+1)*CH + key] = v.y;
        kv_s[(dq+2)*CH + key] = v.z; kv_s[(dq+3)*CH + key] = v.w;
    }
    __syncthreads();

    float acc[3][4];
    #pragma unroll
    for (int i = 0; i < 3; i++)
        #pragma unroll
        for (int j = 0; j < 4; j++) acc[i][j] = 0.f;
    #pragma unroll 8
    for (int d = 0; d < HD; d++) {
        float4 bv = *(const float4*)&kv_s[d*CH + tx*4];
        #pragma unroll
        for (int i = 0; i < 3; i++) {
            float a = qs[(ty*3+i)*HD + d];
            acc[i][0] = fmaf(a, bv.x, acc[i][0]);
            acc[i][1] = fmaf(a, bv.y, acc[i][1]);
            acc[i][2] = fmaf(a, bv.z, acc[i][2]);
            acc[i][3] = fmaf(a, bv.w, acc[i][3]);
        }
    }
    #pragma unroll
    for (int i = 0; i < 3; i++) {
        int q = ty*3 + i;
        int tq = ts[q];
        #pragma unroll
        for (int j = 0; j < 4; j++) {
            int sg = c0 + tx*4 + j;
            S[q*66 + tx*4 + j] = (q < KSEL && sg <= tq) ? acc[i][j] : -1e30f;
        }
    }
    __syncthreads();

    #pragma unroll
    for (int l = 0; l < 4; l++) {
        int fid = tid + l*256;
        int key = fid >> 4;
        int dq  = (fid & 15) << 2;
        *(float4*)&kv_s[key*HD + dq] =
            *(const float4*)&kvb[(size_t)(c0 + key)*NKV + DMODEL + h*HD + dq];
    }
    if (tid < 48) {
        int q = tid;
        float m = -1e30f;
        #pragma unroll 8
        for (int k = 0; k < CH; k++) m = fmaxf(m, S[q*66 + k]);
        float l = 0.f;
        #pragma unroll 8
        for (int k = 0; k < CH; k++) {
            float v = S[q*66 + k];
            float p = (v > -1e29f) ? __expf(v - m) : 0.f;
            S[q*66 + k] = p;
            l += p;
        }
        int base = ((b*NH + h)*NCH + c)*48 + q;
        g_pm[base] = m;
        g_pl[base] = l;
    }
    __syncthreads();

    float acc2[3][4];
    #pragma unroll
    for (int i = 0; i < 3; i++)
        #pragma unroll
        for (int j = 0; j < 4; j++) acc2[i][j] = 0.f;
    #pragma unroll 8
    for (int k = 0; k < CH; k++) {
        float4 bv = *(const float4*)&kv_s[k*HD + tx*4];
        #pragma unroll
        for (int i = 0; i < 3; i++) {
            float a = S[(ty*3+i)*66 + k];
            acc2[i][0] = fmaf(a, bv.x, acc2[i][0]);
            acc2[i][1] = fmaf(a, bv.y, acc2[i][1]);
            acc2[i][2] = fmaf(a, bv.z, acc2[i][2]);
            acc2[i][3] = fmaf(a, bv.w, acc2[i][3]);
        }
    }
    size_t obase = ((size_t)((b*NH + h)*NCH + c))*48;
    #pragma unroll
    for (int i = 0; i < 3; i++) {
        float4 r; r.x = acc2[i][0]; r.y = acc2[i][1]; r.z = acc2[i][2]; r.w = acc2[i][3];
        *(float4*)&g_po[(obase + ty*3 + i)*HD + tx*4] = r;
    }
}

// ============================================================================
__global__ void attn_combine_kernel() {
    int bx = blockIdx.x;
    int q  = bx / NH;
    int h  = bx % NH;
    int b  = q / KSEL;
    int qi = q % KSEL;
    int d  = threadIdx.x;
    int bh = b*NH + h;

    float m = -1e30f;
    #pragma unroll
    for (int c = 0; c < NCH; c++)
        m = fmaxf(m, g_pm[(bh*NCH + c)*48 + qi]);
    float num = 0.f, den = 0.f;
    #pragma unroll
    for (int c = 0; c < NCH; c++) {
        int base = (bh*NCH + c)*48 + qi;
        float w = __expf(g_pm[base] - m);
        den = fmaf(w, g_pl[base], den);
        num = fmaf(w, g_po[(size_t)base*HD + d], num);
    }
    g_ctx[(size_t)q*DMODEL + h*HD + d] = num / den;
}

// ============================================================================
// out projection: full-K loop, gate, plain += into y (each element once)
// ============================================================================
__global__ void __launch_bounds__(256) outproj_kernel(const float* __restrict__ W,
                                                      const float* __restrict__ bias,
                                                      float* __restrict__ y) {
    __shared__ float As[64*48];
    __shared__ float Bs[64*64];
    int tid = threadIdx.x;
    int tx = tid & 15, ty = tid >> 4;
    int cb = blockIdx.x * 64;
    int rt = blockIdx.y;

    float acc[3][4];
    #pragma unroll
    for (int i = 0; i < 3; i++)
        #pragma unroll
        for (int j = 0; j < 4; j++) acc[i][j] = 0.f;

    for (int kb = 0; kb < DMODEL; kb += 64) {
        #pragma unroll
        for (int l = 0; l < 3; l++) {
            int fid = tid + l*256;
            int row = fid >> 4;
            int kc  = (fid & 15) << 2;
            float4 v = *(const float4*)&g_ctx[(size_t)(rt*48 + row)*DMODEL + kb + kc];
            As[(kc+0)*48 + row] = v.x; As[(kc+1)*48 + row] = v.y;
            As[(kc+2)*48 + row] = v.z; As[(kc+3)*48 + row] = v.w;
        }
        #pragma unroll
        for (int l = 0; l < 4; l++) {
            int fid = tid + l*256;
            int kr = fid >> 4;
            int c4 = (fid & 15) << 2;
            *(float4*)&Bs[kr*64 + c4] = *(const float4*)&W[(size_t)(kb + kr)*DMODEL + cb + c4];
        }
        __syncthreads();
        #pragma unroll 8
        for (int k = 0; k < 64; k++) {
            float4 bv = *(const float4*)&Bs[k*64 + tx*4];
            #pragma unroll
            for (int i = 0; i < 3; i++) {
                float a = As[k*48 + ty*3 + i];
                acc[i][0] = fmaf(a, bv.x, acc[i][0]);
                acc[i][1] = fmaf(a, bv.y, acc[i][1]);
                acc[i][2] = fmaf(a, bv.z, acc[i][2]);
                acc[i][3] = fmaf(a, bv.w, acc[i][3]);
            }
        }
        __syncthreads();
    }
    #pragma unroll
    for (int i = 0; i < 3; i++) {
        int row = rt*48 + ty*3 + i;
        if (row < NQ) {
            int b = row / KSEL;
            int t = g_idx[row];
            float p = g_p1[b*SEQL + t];
            float* yr = y + (size_t)(b*SEQL + t)*DMODEL;
            #pragma unroll
            for (int j = 0; j < 4; j++) {
                int col = cb + tx*4 + j;
                yr[col] += p * (acc[i][j] + bias[col]);
            }
        }
    }
}

// ============================================================================
extern "C" void kernel_launch(void* const* d_in, const int* in_sizes, int n_in,
                              void* d_out, int out_size) {
    const float* x     = (const float*)d_in[0];
    const float* Wqkv  = (const float*)d_in[1];
    const float* bqkv  = (const float*)d_in[2];
    const float* sel_w = (const float*)d_in[3];
    const float* sel_b = (const float*)d_in[4];
    const float* out_w = (const float*)d_in[5];
    const float* out_b = (const float*)d_in[6];
    const float* temp  = (const float*)d_in[7];
    float* y = (float*)d_out;

    sel_copy_kernel<<<NROWS, 256>>>(x, sel_w, sel_b, temp, y);
    w_transpose_kernel<<<dim3(NKV/32, DMODEL/32), dim3(32, 8)>>>(Wqkv);
    kv_mma_kernel<<<dim3(NKV/128, NROWS/128), 256>>>(bqkv);
    topk_kernel<<<BATCH, 256>>>();
    qproj_kernel<<<dim3(12, 2), 256>>>(x, Wqkv, bqkv);
    attn_chunk_kernel<<<dim3(NCH, NH, BATCH), 256>>>();
    attn_combine_kernel<<<NQ*NH, HD>>>();
    outproj_kernel<<<dim3(12, 2), 256>>>(out_w, out_b, y);
}

// round 6
// speedup vs baseline: 1.6544x; 1.6544x over previous
#include <cuda_runtime.h>
#include <cuda_bf16.h>
#include <math.h>
#include <stdint.h>

#define BATCH 2
#define SEQL  2048
#define DMODEL 768
#define NH    12
#define HD    64
#define KSEL  46
#define NKV   1536
#define NROWS (BATCH*SEQL)
#define WQKV_COLS 2304
#define NQ    (BATCH*KSEL)
#define NQP   96
#define CH    64
#define NCH   (SEQL/CH)

// -------- scratch --------
__device__ float g_p1[NROWS];
__device__ int   g_idx[NQ];
__device__ int   g_cnt[BATCH];
__device__ float g_kv[(size_t)NROWS * NKV];
__device__ float g_q[NQP*DMODEL];
__device__ float g_ctx[NQP*DMODEL];
__device__ float g_pm[BATCH*NH*NCH*48];
__device__ float g_pl[BATCH*NH*NCH*48];
__device__ float g_po[(size_t)BATCH*NH*NCH*48*HD];
__device__ __nv_bfloat16 g_xb[(size_t)NROWS * DMODEL];   // X bf16 [row][k]
__device__ __nv_bfloat16 g_wt[(size_t)NKV * DMODEL];     // W_kv bf16 [n][k]

__device__ __forceinline__ uint32_t smem_u32(const void* p) {
    uint32_t a;
    asm("{ .reg .u64 t; cvta.to.shared.u64 t, %1; cvt.u32.u64 %0, t; }" : "=r"(a) : "l"(p));
    return a;
}
__device__ __forceinline__ void ldm_x4(uint32_t* r, uint32_t addr) {
    asm volatile("ldmatrix.sync.aligned.m8n8.x4.shared.b16 {%0,%1,%2,%3}, [%4];"
        : "=r"(r[0]), "=r"(r[1]), "=r"(r[2]), "=r"(r[3]) : "r"(addr));
}
__device__ __forceinline__ void mma16816(float* c, const uint32_t* a, uint32_t b0, uint32_t b1) {
    asm volatile(
        "mma.sync.aligned.m16n8k16.row.col.f32.bf16.bf16.f32 "
        "{%0,%1,%2,%3}, {%4,%5,%6,%7}, {%8,%9}, {%0,%1,%2,%3};"
        : "+f"(c[0]), "+f"(c[1]), "+f"(c[2]), "+f"(c[3])
        : "r"(a[0]), "r"(a[1]), "r"(a[2]), "r"(a[3]), "r"(b0), "r"(b1));
}

// ============================================================================
// zero g_q + reset slot counters (independent; launched first)
// ============================================================================
__global__ void zero_kernel() {
    int i = blockIdx.x * 256 + threadIdx.x;
    *(float4*)&g_q[i * 4] = make_float4(0.f, 0.f, 0.f, 0.f);
    if (i < BATCH) g_cnt[i] = 0;
}

// ============================================================================
// sel prob + y=x copy + x->bf16 convert (fused)
// ============================================================================
__global__ void sel_copy_kernel(const float* __restrict__ x,
                                const float* __restrict__ sel_w,
                                const float* __restrict__ sel_b,
                                const float* __restrict__ temp,
                                float* __restrict__ y) {
    int r = blockIdx.x;
    const float* xr = x + (size_t)r * DMODEL;
    float* yr = y + (size_t)r * DMODEL;
    __nv_bfloat16* xb = g_xb + (size_t)r * DMODEL;
    int tid = threadIdx.x;
    float p0 = 0.f, p1 = 0.f;
    #pragma unroll
    for (int j = tid; j < DMODEL; j += 256) {
        float v = xr[j];
        yr[j] = v;
        xb[j] = __float2bfloat16(v);
        float2 w = *(const float2*)&sel_w[2*j];
        p0 = fmaf(v, w.x, p0);
        p1 = fmaf(v, w.y, p1);
    }
    #pragma unroll
    for (int off = 16; off; off >>= 1) {
        p0 += __shfl_down_sync(0xffffffffu, p0, off);
        p1 += __shfl_down_sync(0xffffffffu, p1, off);
    }
    __shared__ float s0[8], s1[8];
    int w = tid >> 5;
    if ((tid & 31) == 0) { s0[w] = p0; s1[w] = p1; }
    __syncthreads();
    if (tid == 0) {
        float a0 = 0.f, a1 = 0.f;
        #pragma unroll
        for (int i = 0; i < 8; i++) { a0 += s0[i]; a1 += s1[i]; }
        a0 += sel_b[0]; a1 += sel_b[1];
        float d = (a1 - a0) / temp[0];
        g_p1[r] = 1.0f / (1.0f + expf(-d));
    }
}

// ============================================================================
// W_kv (cols 768:2304) -> g_wt[n][k] bf16 (transpose)
// ============================================================================
__global__ void w_transpose_kernel(const float* __restrict__ W) {
    __shared__ float t[32][33];
    int n0 = blockIdx.x * 32;
    int k0 = blockIdx.y * 32;
    int tx = threadIdx.x, ty = threadIdx.y;
    #pragma unroll
    for (int i = 0; i < 4; i++)
        t[ty + 8*i][tx] = W[(size_t)(k0 + ty + 8*i) * WQKV_COLS + 768 + n0 + tx];
    __syncthreads();
    #pragma unroll
    for (int i = 0; i < 4; i++)
        g_wt[(size_t)(n0 + ty + 8*i) * DMODEL + k0 + tx] = __float2bfloat16(t[tx][ty + 8*i]);
}

// ============================================================================
// KV GEMM: mma.sync + ldmatrix. CTA 128x128, 8 warps (2M x 4N).
// ============================================================================
#define AST 40

__global__ void __launch_bounds__(256) kv_mma_kernel(const float* __restrict__ bias) {
    __shared__ __nv_bfloat16 sA[128*AST];
    __shared__ __nv_bfloat16 sB[128*AST];
    int tid = threadIdx.x;
    int wid = tid >> 5, lane = tid & 31;
    int wm = wid & 1, wn = wid >> 1;
    int g = lane >> 2, tg = lane & 3;
    int row0 = blockIdx.y * 128;
    int col0 = blockIdx.x * 128;

    int lr0 = tid >> 2, lu = tid & 3;
    const __nv_bfloat16* gA0 = g_xb + (size_t)(row0 + lr0) * DMODEL + lu * 8;
    const __nv_bfloat16* gA1 = g_xb + (size_t)(row0 + lr0 + 64) * DMODEL + lu * 8;
    const __nv_bfloat16* gB0 = g_wt + (size_t)(col0 + lr0) * DMODEL + lu * 8;
    const __nv_bfloat16* gB1 = g_wt + (size_t)(col0 + lr0 + 64) * DMODEL + lu * 8;
    __nv_bfloat16* stA0 = &sA[lr0 * AST + lu * 8];
    __nv_bfloat16* stA1 = &sA[(lr0 + 64) * AST + lu * 8];
    __nv_bfloat16* stB0 = &sB[lr0 * AST + lu * 8];
    __nv_bfloat16* stB1 = &sB[(lr0 + 64) * AST + lu * 8];

    int lrow = lane & 15, lsel = (lane >> 4) * 8;
    uint32_t aBase = smem_u32(sA) + (uint32_t)(((wm*64 + lrow) * AST + lsel) * 2);
    uint32_t bBase = smem_u32(sB) + (uint32_t)(((wn*32 + lrow) * AST + lsel) * 2);

    float c[4][4][4];
    #pragma unroll
    for (int mi = 0; mi < 4; mi++)
        #pragma unroll
        for (int ni = 0; ni < 4; ni++)
            #pragma unroll
            for (int j = 0; j < 4; j++) c[mi][ni][j] = 0.f;

    uint4 pA0 = *(const uint4*)gA0, pA1 = *(const uint4*)gA1;
    uint4 pB0 = *(const uint4*)gB0, pB1 = *(const uint4*)gB1;

    for (int kc = 0; kc < 24; kc++) {
        *(uint4*)stA0 = pA0; *(uint4*)stA1 = pA1;
        *(uint4*)stB0 = pB0; *(uint4*)stB1 = pB1;
        __syncthreads();
        if (kc < 23) {
            int k0 = (kc + 1) * 32;
            pA0 = *(const uint4*)(gA0 + k0); pA1 = *(const uint4*)(gA1 + k0);
            pB0 = *(const uint4*)(gB0 + k0); pB1 = *(const uint4*)(gB1 + k0);
        }
        #pragma unroll
        for (int ks = 0; ks < 2; ks++) {
            uint32_t A[4][4], Bf[2][4];
            #pragma unroll
            for (int mi = 0; mi < 4; mi++)
                ldm_x4(A[mi], aBase + (uint32_t)((mi*16*AST + ks*16) * 2));
            #pragma unroll
            for (int bi = 0; bi < 2; bi++)
                ldm_x4(Bf[bi], bBase + (uint32_t)((bi*16*AST + ks*16) * 2));
            #pragma unroll
            for (int mi = 0; mi < 4; mi++) {
                mma16816(c[mi][0], A[mi], Bf[0][0], Bf[0][2]);
                mma16816(c[mi][1], A[mi], Bf[0][1], Bf[0][3]);
                mma16816(c[mi][2], A[mi], Bf[1][0], Bf[1][2]);
                mma16816(c[mi][3], A[mi], Bf[1][1], Bf[1][3]);
            }
        }
        __syncthreads();
    }

    #pragma unroll
    for (int mi = 0; mi < 4; mi++) {
        int row = row0 + wm * 64 + mi * 16;
        #pragma unroll
        for (int ni = 0; ni < 4; ni++) {
            int col = col0 + wn * 32 + ni * 8 + 2 * tg;
            float2 bb = *(const float2*)&bias[768 + col];
            float2 r0, r1;
            r0.x = c[mi][ni][0] + bb.x; r0.y = c[mi][ni][1] + bb.y;
            r1.x = c[mi][ni][2] + bb.x; r1.y = c[mi][ni][3] + bb.y;
            *(float2*)&g_kv[(size_t)(row + g) * NKV + col] = r0;
            *(float2*)&g_kv[(size_t)(row + g + 8) * NKV + col] = r1;
        }
    }
}

// ============================================================================
// rank-select top-KSEL: element selected iff rank < KSEL.
// rank = #{j: p[j] > p[i] || (p[j]==p[i] && j<i)} (jax tie-break).
// Selected SET is what matters; slot order is irrelevant to the output.
// grid (SEQL/64, BATCH), 256 threads; warp ranks 8 candidates.
// ============================================================================
__global__ void __launch_bounds__(256) ranksel_kernel() {
    int b = blockIdx.y;
    __shared__ float vals[SEQL];
    int tid = threadIdx.x;
    int warp = tid >> 5, lane = tid & 31;
    #pragma unroll
    for (int l = 0; l < 8; l++) vals[tid + l * 256] = g_p1[b * SEQL + tid + l * 256];
    __syncthreads();
    #pragma unroll
    for (int i = 0; i < 8; i++) {
        int cand = blockIdx.x * 64 + warp * 8 + i;
        float v = vals[cand];
        int cnt = 0;
        #pragma unroll
        for (int l = 0; l < 64; l++) {
            int j = lane + l * 32;
            float u = vals[j];
            cnt += (u > v || (u == v && j < cand)) ? 1 : 0;
        }
        #pragma unroll
        for (int off = 16; off; off >>= 1)
            cnt += __shfl_xor_sync(0xffffffffu, cnt, off);
        if (lane == 0 && cnt < KSEL) {
            int slot = atomicAdd(&g_cnt[b], 1);
            g_idx[b * KSEL + slot] = cand;
        }
    }
}

// ============================================================================
// Q projection: gathered rows from x, k-split (z), atomicAdd into zeroed g_q.
// grid (12 coltiles, 2 rowtiles, 12 ksplits)
// ============================================================================
__global__ void __launch_bounds__(256) qproj_kernel(const float* __restrict__ x,
                                                    const float* __restrict__ W,
                                                    const float* __restrict__ bias) {
    __shared__ float As[64*48];
    __shared__ float Bs[64*64];
    __shared__ int rowsrc[48];
    int tid = threadIdx.x;
    int tx = tid & 15, ty = tid >> 4;
    int cb = blockIdx.x * 64;
    int rt = blockIdx.y;
    int kb = blockIdx.z * 64;
    if (tid < 48) {
        int r = rt*48 + tid;
        rowsrc[tid] = (r < NQ) ? ((r / KSEL) * SEQL + g_idx[r]) : -1;
    }
    __syncthreads();

    #pragma unroll
    for (int l = 0; l < 3; l++) {
        int fid = tid + l*256;
        int row = fid >> 4;
        int kc  = (fid & 15) << 2;
        int src = rowsrc[row];
        float4 v = make_float4(0.f, 0.f, 0.f, 0.f);
        if (src >= 0) v = *(const float4*)&x[(size_t)src*DMODEL + kb + kc];
        As[(kc+0)*48 + row] = v.x; As[(kc+1)*48 + row] = v.y;
        As[(kc+2)*48 + row] = v.z; As[(kc+3)*48 + row] = v.w;
    }
    #pragma unroll
    for (int l = 0; l < 4; l++) {
        int fid = tid + l*256;
        int kr = fid >> 4;
        int c4 = (fid & 15) << 2;
        *(float4*)&Bs[kr*64 + c4] = *(const float4*)&W[(size_t)(kb + kr)*WQKV_COLS + cb + c4];
    }
    __syncthreads();
    float acc[3][4];
    #pragma unroll
    for (int i = 0; i < 3; i++)
        #pragma unroll
        for (int j = 0; j < 4; j++) acc[i][j] = 0.f;
    #pragma unroll 8
    for (int k = 0; k < 64; k++) {
        float4 bv = *(const float4*)&Bs[k*64 + tx*4];
        #pragma unroll
        for (int i = 0; i < 3; i++) {
            float a = As[k*48 + ty*3 + i];
            acc[i][0] = fmaf(a, bv.x, acc[i][0]);
            acc[i][1] = fmaf(a, bv.y, acc[i][1]);
            acc[i][2] = fmaf(a, bv.z, acc[i][2]);
            acc[i][3] = fmaf(a, bv.w, acc[i][3]);
        }
    }
    #pragma unroll
    for (int i = 0; i < 3; i++) {
        int row = rt*48 + ty*3 + i;
        if (row < NQ) {
            #pragma unroll
            for (int j = 0; j < 4; j++) {
                int col = cb + tx*4 + j;
                float v = acc[i][j] + (blockIdx.z == 0 ? bias[col] : 0.f);
                atomicAdd(&g_q[(size_t)row*DMODEL + col], v);
            }
        }
    }
}

// ============================================================================
// flash-decode attention chunk (fp32)
// ============================================================================
__global__ void __launch_bounds__(256) attn_chunk_kernel() {
    int c  = blockIdx.x;
    int h  = blockIdx.y;
    int b  = blockIdx.z;
    int c0 = c * CH;
    int tid = threadIdx.x;
    int tx = tid & 15, ty = tid >> 4;

    __shared__ float qs[48*HD];
    __shared__ float kv_s[CH*HD];
    __shared__ float S[48*66];
    __shared__ int   ts[48];

    if (tid < 48) ts[tid] = (tid < KSEL) ? g_idx[b*KSEL + tid] : -1;
    for (int idx = tid; idx < 48*HD; idx += 256) {
        int q = idx >> 6, d = idx & 63;
        qs[idx] = (q < KSEL) ? g_q[(size_t)(b*KSEL + q)*DMODEL + h*HD + d] * 0.125f : 0.f;
    }
    const float* kvb = g_kv + (size_t)b * SEQL * NKV;
    #pragma unroll
    for (int l = 0; l < 4; l++) {
        int fid = tid + l*256;
        int key = fid >> 4;
        int dq  = (fid & 15) << 2;
        float4 v = *(const float4*)&kvb[(size_t)(c0 + key)*NKV + h*HD + dq];
        kv_s[(dq+0)*CH + key] = v.x; kv_s[(dq+1)*CH + key] = v.y;
        kv_s[(dq+2)*CH + key] = v.z; kv_s[(dq+3)*CH + key] = v.w;
    }
    __syncthreads();

    float acc[3][4];
    #pragma unroll
    for (int i = 0; i < 3; i++)
        #pragma unroll
        for (int j = 0; j < 4; j++) acc[i][j] = 0.f;
    #pragma unroll 8
    for (int d = 0; d < HD; d++) {
        float4 bv = *(const float4*)&kv_s[d*CH + tx*4];
        #pragma unroll
        for (int i = 0; i < 3; i++) {
            float a = qs[(ty*3+i)*HD + d];
            acc[i][0] = fmaf(a, bv.x, acc[i][0]);
            acc[i][1] = fmaf(a, bv.y, acc[i][1]);
            acc[i][2] = fmaf(a, bv.z, acc[i][2]);
            acc[i][3] = fmaf(a, bv.w, acc[i][3]);
        }
    }
    #pragma unroll
    for (int i = 0; i < 3; i++) {
        int q = ty*3 + i;
        int tq = ts[q];
        #pragma unroll
        for (int j = 0; j < 4; j++) {
            int sg = c0 + tx*4 + j;
            S[q*66 + tx*4 + j] = (q < KSEL && sg <= tq) ? acc[i][j] : -1e30f;
        }
    }
    __syncthreads();

    #pragma unroll
    for (int l = 0; l < 4; l++) {
        int fid = tid + l*256;
        int key = fid >> 4;
        int dq  = (fid & 15) << 2;
        *(float4*)&kv_s[key*HD + dq] =
            *(const float4*)&kvb[(size_t)(c0 + key)*NKV + DMODEL + h*HD + dq];
    }
    if (tid < 48) {
        int q = tid;
        float m = -1e30f;
        #pragma unroll 8
        for (int k = 0; k < CH; k++) m = fmaxf(m, S[q*66 + k]);
        float l = 0.f;
        #pragma unroll 8
        for (int k = 0; k < CH; k++) {
            float v = S[q*66 + k];
            float p = (v > -1e29f) ? __expf(v - m) : 0.f;
            S[q*66 + k] = p;
            l += p;
        }
        int base = ((b*NH + h)*NCH + c)*48 + q;
        g_pm[base] = m;
        g_pl[base] = l;
    }
    __syncthreads();

    float acc2[3][4];
    #pragma unroll
    for (int i = 0; i < 3; i++)
        #pragma unroll
        for (int j = 0; j < 4; j++) acc2[i][j] = 0.f;
    #pragma unroll 8
    for (int k = 0; k < CH; k++) {
        float4 bv = *(const float4*)&kv_s[k*HD + tx*4];
        #pragma unroll
        for (int i = 0; i < 3; i++) {
            float a = S[(ty*3+i)*66 + k];
            acc2[i][0] = fmaf(a, bv.x, acc2[i][0]);
            acc2[i][1] = fmaf(a, bv.y, acc2[i][1]);
            acc2[i][2] = fmaf(a, bv.z, acc2[i][2]);
            acc2[i][3] = fmaf(a, bv.w, acc2[i][3]);
        }
    }
    size_t obase = ((size_t)((b*NH + h)*NCH + c))*48;
    #pragma unroll
    for (int i = 0; i < 3; i++) {
        float4 r; r.x = acc2[i][0]; r.y = acc2[i][1]; r.z = acc2[i][2]; r.w = acc2[i][3];
        *(float4*)&g_po[(obase + ty*3 + i)*HD + tx*4] = r;
    }
}

// ============================================================================
__global__ void attn_combine_kernel() {
    int bx = blockIdx.x;
    int q  = bx / NH;
    int h  = bx % NH;
    int b  = q / KSEL;
    int qi = q % KSEL;
    int d  = threadIdx.x;
    int bh = b*NH + h;

    float m = -1e30f;
    #pragma unroll
    for (int c = 0; c < NCH; c++)
        m = fmaxf(m, g_pm[(bh*NCH + c)*48 + qi]);
    float num = 0.f, den = 0.f;
    #pragma unroll
    for (int c = 0; c < NCH; c++) {
        int base = (bh*NCH + c)*48 + qi;
        float w = __expf(g_pm[base] - m);
        den = fmaf(w, g_pl[base], den);
        num = fmaf(w, g_po[(size_t)base*HD + d], num);
    }
    g_ctx[(size_t)q*DMODEL + h*HD + d] = num / den;
}

// ============================================================================
// out projection: k-split (z), gate, atomicAdd into y
// ============================================================================
__global__ void __launch_bounds__(256) outproj_kernel(const float* __restrict__ W,
                                                      const float* __restrict__ bias,
                                                      float* __restrict__ y) {
    __shared__ float As[64*48];
    __shared__ float Bs[64*64];
    int tid = threadIdx.x;
    int tx = tid & 15, ty = tid >> 4;
    int cb = blockIdx.x * 64;
    int rt = blockIdx.y;
    int kb = blockIdx.z * 64;

    #pragma unroll
    for (int l = 0; l < 3; l++) {
        int fid = tid + l*256;
        int row = fid >> 4;
        int kc  = (fid & 15) << 2;
        float4 v = *(const float4*)&g_ctx[(size_t)(rt*48 + row)*DMODEL + kb + kc];
        As[(kc+0)*48 + row] = v.x; As[(kc+1)*48 + row] = v.y;
        As[(kc+2)*48 + row] = v.z; As[(kc+3)*48 + row] = v.w;
    }
    #pragma unroll
    for (int l = 0; l < 4; l++) {
        int fid = tid + l*256;
        int kr = fid >> 4;
        int c4 = (fid & 15) << 2;
        *(float4*)&Bs[kr*64 + c4] = *(const float4*)&W[(size_t)(kb + kr)*DMODEL + cb + c4];
    }
    __syncthreads();
    float acc[3][4];
    #pragma unroll
    for (int i = 0; i < 3; i++)
        #pragma unroll
        for (int j = 0; j < 4; j++) acc[i][j] = 0.f;
    #pragma unroll 8
    for (int k = 0; k < 64; k++) {
        float4 bv = *(const float4*)&Bs[k*64 + tx*4];
        #pragma unroll
        for (int i = 0; i < 3; i++) {
            float a = As[k*48 + ty*3 + i];
            acc[i][0] = fmaf(a, bv.x, acc[i][0]);
            acc[i][1] = fmaf(a, bv.y, acc[i][1]);
            acc[i][2] = fmaf(a, bv.z, acc[i][2]);
            acc[i][3] = fmaf(a, bv.w, acc[i][3]);
        }
    }
    #pragma unroll
    for (int i = 0; i < 3; i++) {
        int row = rt*48 + ty*3 + i;
        if (row < NQ) {
            int b = row / KSEL;
            int t = g_idx[row];
            float p = g_p1[b*SEQL + t];
            float* yr = y + (size_t)(b*SEQL + t)*DMODEL;
            #pragma unroll
            for (int j = 0; j < 4; j++) {
                int col = cb + tx*4 + j;
                float v = acc[i][j] + (blockIdx.z == 0 ? bias[col] : 0.f);
                atomicAdd(&yr[col], p * v);
            }
        }
    }
}

// ============================================================================
extern "C" void kernel_launch(void* const* d_in, const int* in_sizes, int n_in,
                              void* d_out, int out_size) {
    const float* x     = (const float*)d_in[0];
    const float* Wqkv  = (const float*)d_in[1];
    const float* bqkv  = (const float*)d_in[2];
    const float* sel_w = (const float*)d_in[3];
    const float* sel_b = (const float*)d_in[4];
    const float* out_w = (const float*)d_in[5];
    const float* out_b = (const float*)d_in[6];
    const float* temp  = (const float*)d_in[7];
    float* y = (float*)d_out;

    zero_kernel<<<NQP*DMODEL/1024, 256>>>();
    sel_copy_kernel<<<NROWS, 256>>>(x, sel_w, sel_b, temp, y);
    w_transpose_kernel<<<dim3(NKV/32, DMODEL/32), dim3(32, 8)>>>(Wqkv);
    kv_mma_kernel<<<dim3(NKV/128, NROWS/128), 256>>>(bqkv);
    ranksel_kernel<<<dim3(SEQL/64, BATCH), 256>>>();
    qproj_kernel<<<dim3(12, 2, 12), 256>>>(x, Wqkv, bqkv);
    attn_chunk_kernel<<<dim3(NCH, NH, BATCH), 256>>>();
    attn_combine_kernel<<<NQ*NH, HD>>>();
    outproj_kernel<<<dim3(12, 2, 12), 256>>>(out_w, out_b, y);
}

// round 8
// speedup vs baseline: 1.6741x; 1.0119x over previous
#include <cuda_runtime.h>
#include <cuda_bf16.h>
#include <math.h>
#include <stdint.h>

#define BATCH 2
#define SEQL  2048
#define DMODEL 768
#define NH    12
#define HD    64
#define KSEL  46
#define NKV   1536
#define NROWS (BATCH*SEQL)
#define WQKV_COLS 2304
#define NQ    (BATCH*KSEL)
#define NQP   96
#define CH    64
#define NCH   (SEQL/CH)

// -------- scratch --------
__device__ float g_p1[NROWS];
__device__ int   g_idx[NQ];
__device__ int   g_cnt[BATCH];
__device__ float g_kv[(size_t)NROWS * NKV];
__device__ float g_q[NQP*DMODEL];
__device__ float g_ctx[NQP*DMODEL];
__device__ float g_pm[BATCH*NH*NCH*48];
__device__ float g_pl[BATCH*NH*NCH*48];
__device__ float g_po[(size_t)BATCH*NH*NCH*48*HD];
__device__ __nv_bfloat16 g_xb[(size_t)NROWS * DMODEL];   // X bf16 [row][k]
__device__ __nv_bfloat16 g_wt[(size_t)NKV * DMODEL];     // W_kv bf16 [n][k]

__device__ __forceinline__ uint32_t smem_u32(const void* p) {
    uint32_t a;
    asm("{ .reg .u64 t; cvta.to.shared.u64 t, %1; cvt.u32.u64 %0, t; }" : "=r"(a) : "l"(p));
    return a;
}
__device__ __forceinline__ void ldm_x4(uint32_t* r, uint32_t addr) {
    asm volatile("ldmatrix.sync.aligned.m8n8.x4.shared.b16 {%0,%1,%2,%3}, [%4];"
        : "=r"(r[0]), "=r"(r[1]), "=r"(r[2]), "=r"(r[3]) : "r"(addr));
}
__device__ __forceinline__ void mma16816(float* c, const uint32_t* a, uint32_t b0, uint32_t b1) {
    asm volatile(
        "mma.sync.aligned.m16n8k16.row.col.f32.bf16.bf16.f32 "
        "{%0,%1,%2,%3}, {%4,%5,%6,%7}, {%8,%9}, {%0,%1,%2,%3};"
        : "+f"(c[0]), "+f"(c[1]), "+f"(c[2]), "+f"(c[3])
        : "r"(a[0]), "r"(a[1]), "r"(a[2]), "r"(a[3]), "r"(b0), "r"(b1));
}
#define CP_ASYNC16(dst, src) \
    asm volatile("cp.async.cg.shared.global [%0], [%1], 16;" :: "r"(dst), "l"(src))
#define CP_COMMIT() asm volatile("cp.async.commit_group;" ::: "memory")
#define CP_WAIT0()  asm volatile("cp.async.wait_group 0;" ::: "memory")

// ============================================================================
// zero g_q + reset slot counters
// ============================================================================
__global__ void zero_kernel() {
    int i = blockIdx.x * 256 + threadIdx.x;
    *(float4*)&g_q[i * 4] = make_float4(0.f, 0.f, 0.f, 0.f);
    if (i < BATCH) g_cnt[i] = 0;
}

// ============================================================================
// sel prob + y=x copy + x->bf16 convert (fused)
// ============================================================================
__global__ void sel_copy_kernel(const float* __restrict__ x,
                                const float* __restrict__ sel_w,
                                const float* __restrict__ sel_b,
                                const float* __restrict__ temp,
                                float* __restrict__ y) {
    int r = blockIdx.x;
    const float* xr = x + (size_t)r * DMODEL;
    float* yr = y + (size_t)r * DMODEL;
    __nv_bfloat16* xb = g_xb + (size_t)r * DMODEL;
    int tid = threadIdx.x;
    float p0 = 0.f, p1 = 0.f;
    #pragma unroll
    for (int j = tid; j < DMODEL; j += 256) {
        float v = xr[j];
        yr[j] = v;
        xb[j] = __float2bfloat16(v);
        float2 w = *(const float2*)&sel_w[2*j];
        p0 = fmaf(v, w.x, p0);
        p1 = fmaf(v, w.y, p1);
    }
    #pragma unroll
    for (int off = 16; off; off >>= 1) {
        p0 += __shfl_down_sync(0xffffffffu, p0, off);
        p1 += __shfl_down_sync(0xffffffffu, p1, off);
    }
    __shared__ float s0[8], s1[8];
    int w = tid >> 5;
    if ((tid & 31) == 0) { s0[w] = p0; s1[w] = p1; }
    __syncthreads();
    if (tid == 0) {
        float a0 = 0.f, a1 = 0.f;
        #pragma unroll
        for (int i = 0; i < 8; i++) { a0 += s0[i]; a1 += s1[i]; }
        a0 += sel_b[0]; a1 += sel_b[1];
        float d = (a1 - a0) / temp[0];
        g_p1[r] = 1.0f / (1.0f + expf(-d));
    }
}

// ============================================================================
// W_kv (cols 768:2304) -> g_wt[n][k] bf16 (transpose)
// ============================================================================
__global__ void w_transpose_kernel(const float* __restrict__ W) {
    __shared__ float t[32][33];
    int n0 = blockIdx.x * 32;
    int k0 = blockIdx.y * 32;
    int tx = threadIdx.x, ty = threadIdx.y;
    #pragma unroll
    for (int i = 0; i < 4; i++)
        t[ty + 8*i][tx] = W[(size_t)(k0 + ty + 8*i) * WQKV_COLS + 768 + n0 + tx];
    __syncthreads();
    #pragma unroll
    for (int i = 0; i < 4; i++)
        g_wt[(size_t)(n0 + ty + 8*i) * DMODEL + k0 + tx] = __float2bfloat16(t[tx][ty + 8*i]);
}

// ============================================================================
// KV GEMM: cp.async 2-stage pipeline + ldmatrix + mma.sync.
// CTA 128x128, 8 warps (2M x 4N), K-chunk 32.
// Loader: 2 threads/row; thread half h covers elements [h*16, h*16+16).
// ============================================================================
#define AST 40
#define STAGE_ELEMS (128*AST)

__global__ void __launch_bounds__(256) kv_mma_kernel(const float* __restrict__ bias) {
    __shared__ __nv_bfloat16 sA[2*STAGE_ELEMS];
    __shared__ __nv_bfloat16 sB[2*STAGE_ELEMS];
    int tid = threadIdx.x;
    int wid = tid >> 5, lane = tid & 31;
    int wm = wid & 1, wn = wid >> 1;
    int g = lane >> 2, tg = lane & 3;
    int row0 = blockIdx.y * 128;
    int col0 = blockIdx.x * 128;

    // cp.async loader coords: per chunk each row = 32 bf16 = 64 B = 4x16B units.
    // 2 threads per row; thread half lh in elements {0,16}; copies lh and lh+8.
    int lr = tid >> 1;                 // 0..127
    int lh = (tid & 1) * 16;           // element offset
    const __nv_bfloat16* gA = g_xb + (size_t)(row0 + lr) * DMODEL + lh;
    const __nv_bfloat16* gB = g_wt + (size_t)(col0 + lr) * DMODEL + lh;
    uint32_t stA = smem_u32(sA) + (uint32_t)((lr * AST + lh) * 2);
    uint32_t stB = smem_u32(sB) + (uint32_t)((lr * AST + lh) * 2);

    // ldmatrix lane addressing
    int lrow = lane & 15, lsel = (lane >> 4) * 8;
    uint32_t aBase = smem_u32(sA) + (uint32_t)(((wm*64 + lrow) * AST + lsel) * 2);
    uint32_t bBase = smem_u32(sB) + (uint32_t)(((wn*32 + lrow) * AST + lsel) * 2);

    float c[4][4][4];
    #pragma unroll
    for (int mi = 0; mi < 4; mi++)
        #pragma unroll
        for (int ni = 0; ni < 4; ni++)
            #pragma unroll
            for (int j = 0; j < 4; j++) c[mi][ni][j] = 0.f;

    // prologue: stage 0
    CP_ASYNC16(stA, gA);           CP_ASYNC16(stA + 16, gA + 8);
    CP_ASYNC16(stB, gB);           CP_ASYNC16(stB + 16, gB + 8);
    CP_COMMIT();

    for (int kc = 0; kc < 24; kc++) {
        CP_WAIT0();
        __syncthreads();
        if (kc < 23) {
            int k0 = (kc + 1) * 32;
            uint32_t so = (uint32_t)(((kc + 1) & 1) * STAGE_ELEMS * 2);
            CP_ASYNC16(stA + so, gA + k0);      CP_ASYNC16(stA + so + 16, gA + k0 + 8);
            CP_ASYNC16(stB + so, gB + k0);      CP_ASYNC16(stB + so + 16, gB + k0 + 8);
            CP_COMMIT();
        }
        uint32_t so = (uint32_t)((kc & 1) * STAGE_ELEMS * 2);
        #pragma unroll
        for (int ks = 0; ks < 2; ks++) {
            uint32_t A[4][4], Bf[2][4];
            #pragma unroll
            for (int mi = 0; mi < 4; mi++)
                ldm_x4(A[mi], aBase + so + (uint32_t)((mi*16*AST + ks*16) * 2));
            #pragma unroll
            for (int bi = 0; bi < 2; bi++)
                ldm_x4(Bf[bi], bBase + so + (uint32_t)((bi*16*AST + ks*16) * 2));
            #pragma unroll
            for (int mi = 0; mi < 4; mi++) {
                mma16816(c[mi][0], A[mi], Bf[0][0], Bf[0][2]);
                mma16816(c[mi][1], A[mi], Bf[0][1], Bf[0][3]);
                mma16816(c[mi][2], A[mi], Bf[1][0], Bf[1][2]);
                mma16816(c[mi][3], A[mi], Bf[1][1], Bf[1][3]);
            }
        }
    }

    #pragma unroll
    for (int mi = 0; mi < 4; mi++) {
        int row = row0 + wm * 64 + mi * 16;
        #pragma unroll
        for (int ni = 0; ni < 4; ni++) {
            int col = col0 + wn * 32 + ni * 8 + 2 * tg;
            float2 bb = *(const float2*)&bias[768 + col];
            float2 r0, r1;
            r0.x = c[mi][ni][0] + bb.x; r0.y = c[mi][ni][1] + bb.y;
            r1.x = c[mi][ni][2] + bb.x; r1.y = c[mi][ni][3] + bb.y;
            *(float2*)&g_kv[(size_t)(row + g) * NKV + col] = r0;
            *(float2*)&g_kv[(size_t)(row + g + 8) * NKV + col] = r1;
        }
    }
}

// ============================================================================
// rank-select top-KSEL (jax tie-break); slot order irrelevant downstream.
// ============================================================================
__global__ void __launch_bounds__(256) ranksel_kernel() {
    int b = blockIdx.y;
    __shared__ float vals[SEQL];
    int tid = threadIdx.x;
    int warp = tid >> 5, lane = tid & 31;
    #pragma unroll
    for (int l = 0; l < 8; l++) vals[tid + l * 256] = g_p1[b * SEQL + tid + l * 256];
    __syncthreads();
    #pragma unroll
    for (int i = 0; i < 8; i++) {
        int cand = blockIdx.x * 64 + warp * 8 + i;
        float v = vals[cand];
        int cnt = 0;
        #pragma unroll
        for (int l = 0; l < 64; l++) {
            int j = lane + l * 32;
            float u = vals[j];
            cnt += (u > v || (u == v && j < cand)) ? 1 : 0;
        }
        #pragma unroll
        for (int off = 16; off; off >>= 1)
            cnt += __shfl_xor_sync(0xffffffffu, cnt, off);
        if (lane == 0 && cnt < KSEL) {
            int slot = atomicAdd(&g_cnt[b], 1);
            g_idx[b * KSEL + slot] = cand;
        }
    }
}

// ============================================================================
// Q projection: gathered rows from x, k-split (z), atomicAdd into zeroed g_q.
// ============================================================================
__global__ void __launch_bounds__(256) qproj_kernel(const float* __restrict__ x,
                                                    const float* __restrict__ W,
                                                    const float* __restrict__ bias) {
    __shared__ float As[64*48];
    __shared__ float Bs[64*64];
    __shared__ int rowsrc[48];
    int tid = threadIdx.x;
    int tx = tid & 15, ty = tid >> 4;
    int cb = blockIdx.x * 64;
    int rt = blockIdx.y;
    int kb = blockIdx.z * 64;
    if (tid < 48) {
        int r = rt*48 + tid;
        rowsrc[tid] = (r < NQ) ? ((r / KSEL) * SEQL + g_idx[r]) : -1;
    }
    __syncthreads();

    #pragma unroll
    for (int l = 0; l < 3; l++) {
        int fid = tid + l*256;
        int row = fid >> 4;
        int kc  = (fid & 15) << 2;
        int src = rowsrc[row];
        float4 v = make_float4(0.f, 0.f, 0.f, 0.f);
        if (src >= 0) v = *(const float4*)&x[(size_t)src*DMODEL + kb + kc];
        As[(kc+0)*48 + row] = v.x; As[(kc+1)*48 + row] = v.y;
        As[(kc+2)*48 + row] = v.z; As[(kc+3)*48 + row] = v.w;
    }
    #pragma unroll
    for (int l = 0; l < 4; l++) {
        int fid = tid + l*256;
        int kr = fid >> 4;
        int c4 = (fid & 15) << 2;
        *(float4*)&Bs[kr*64 + c4] = *(const float4*)&W[(size_t)(kb + kr)*WQKV_COLS + cb + c4];
    }
    __syncthreads();
    float acc[3][4];
    #pragma unroll
    for (int i = 0; i < 3; i++)
        #pragma unroll
        for (int j = 0; j < 4; j++) acc[i][j] = 0.f;
    #pragma unroll 8
    for (int k = 0; k < 64; k++) {
        float4 bv = *(const float4*)&Bs[k*64 + tx*4];
        #pragma unroll
        for (int i = 0; i < 3; i++) {
            float a = As[k*48 + ty*3 + i];
            acc[i][0] = fmaf(a, bv.x, acc[i][0]);
            acc[i][1] = fmaf(a, bv.y, acc[i][1]);
            acc[i][2] = fmaf(a, bv.z, acc[i][2]);
            acc[i][3] = fmaf(a, bv.w, acc[i][3]);
        }
    }
    #pragma unroll
    for (int i = 0; i < 3; i++) {
        int row = rt*48 + ty*3 + i;
        if (row < NQ) {
            #pragma unroll
            for (int j = 0; j < 4; j++) {
                int col = cb + tx*4 + j;
                float v = acc[i][j] + (blockIdx.z == 0 ? bias[col] : 0.f);
                atomicAdd(&g_q[(size_t)row*DMODEL + col], v);
            }
        }
    }
}

// ============================================================================
// flash-decode attention chunk (fp32)
// ============================================================================
__global__ void __launch_bounds__(256) attn_chunk_kernel() {
    int c  = blockIdx.x;
    int h  = blockIdx.y;
    int b  = blockIdx.z;
    int c0 = c * CH;
    int tid = threadIdx.x;
    int tx = tid & 15, ty = tid >> 4;

    __shared__ float qs[48*HD];
    __shared__ float kv_s[CH*HD];
    __shared__ float S[48*66];
    __shared__ int   ts[48];

    if (tid < 48) ts[tid] = (tid < KSEL) ? g_idx[b*KSEL + tid] : -1;
    for (int idx = tid; idx < 48*HD; idx += 256) {
        int q = idx >> 6, d = idx & 63;
        qs[idx] = (q < KSEL) ? g_q[(size_t)(b*KSEL + q)*DMODEL + h*HD + d] * 0.125f : 0.f;
    }
    const float* kvb = g_kv + (size_t)b * SEQL * NKV;
    #pragma unroll
    for (int l = 0; l < 4; l++) {
        int fid = tid + l*256;
        int key = fid >> 4;
        int dq  = (fid & 15) << 2;
        float4 v = *(const float4*)&kvb[(size_t)(c0 + key)*NKV + h*HD + dq];
        kv_s[(dq+0)*CH + key] = v.x; kv_s[(dq+1)*CH + key] = v.y;
        kv_s[(dq+2)*CH + key] = v.z; kv_s[(dq+3)*CH + key] = v.w;
    }
    __syncthreads();

    float acc[3][4];
    #pragma unroll
    for (int i = 0; i < 3; i++)
        #pragma unroll
        for (int j = 0; j < 4; j++) acc[i][j] = 0.f;
    #pragma unroll 8
    for (int d = 0; d < HD; d++) {
        float4 bv = *(const float4*)&kv_s[d*CH + tx*4];
        #pragma unroll
        for (int i = 0; i < 3; i++) {
            float a = qs[(ty*3+i)*HD + d];
            acc[i][0] = fmaf(a, bv.x, acc[i][0]);
            acc[i][1] = fmaf(a, bv.y, acc[i][1]);
            acc[i][2] = fmaf(a, bv.z, acc[i][2]);
            acc[i][3] = fmaf(a, bv.w, acc[i][3]);
        }
    }
    #pragma unroll
    for (int i = 0; i < 3; i++) {
        int q = ty*3 + i;
        int tq = ts[q];
        #pragma unroll
        for (int j = 0; j < 4; j++) {
            int sg = c0 + tx*4 + j;
            S[q*66 + tx*4 + j] = (q < KSEL && sg <= tq) ? acc[i][j] : -1e30f;
        }
    }
    __syncthreads();

    #pragma unroll
    for (int l = 0; l < 4; l++) {
        int fid = tid + l*256;
        int key = fid >> 4;
        int dq  = (fid & 15) << 2;
        *(float4*)&kv_s[key*HD + dq] =
            *(const float4*)&kvb[(size_t)(c0 + key)*NKV + DMODEL + h*HD + dq];
    }
    if (tid < 48) {
        int q = tid;
        float m = -1e30f;
        #pragma unroll 8
        for (int k = 0; k < CH; k++) m = fmaxf(m, S[q*66 + k]);
        float l = 0.f;
        #pragma unroll 8
        for (int k = 0; k < CH; k++) {
            float v = S[q*66 + k];
            float p = (v > -1e29f) ? __expf(v - m) : 0.f;
            S[q*66 + k] = p;
            l += p;
        }
        int base = ((b*NH + h)*NCH + c)*48 + q;
        g_pm[base] = m;
        g_pl[base] = l;
    }
    __syncthreads();

    float acc2[3][4];
    #pragma unroll
    for (int i = 0; i < 3; i++)
        #pragma unroll
        for (int j = 0; j < 4; j++) acc2[i][j] = 0.f;
    #pragma unroll 8
    for (int k = 0; k < CH; k++) {
        float4 bv = *(const float4*)&kv_s[k*HD + tx*4];
        #pragma unroll
        for (int i = 0; i < 3; i++) {
            float a = S[(ty*3+i)*66 + k];
            acc2[i][0] = fmaf(a, bv.x, acc2[i][0]);
            acc2[i][1] = fmaf(a, bv.y, acc2[i][1]);
            acc2[i][2] = fmaf(a, bv.z, acc2[i][2]);
            acc2[i][3] = fmaf(a, bv.w, acc2[i][3]);
        }
    }
    size_t obase = ((size_t)((b*NH + h)*NCH + c))*48;
    #pragma unroll
    for (int i = 0; i < 3; i++) {
        float4 r; r.x = acc2[i][0]; r.y = acc2[i][1]; r.z = acc2[i][2]; r.w = acc2[i][3];
        *(float4*)&g_po[(obase + ty*3 + i)*HD + tx*4] = r;
    }
}

// ============================================================================
__global__ void attn_combine_kernel() {
    int bx = blockIdx.x;
    int q  = bx / NH;
    int h  = bx % NH;
    int b  = q / KSEL;
    int qi = q % KSEL;
    int d  = threadIdx.x;
    int bh = b*NH + h;

    float m = -1e30f;
    #pragma unroll
    for (int c = 0; c < NCH; c++)
        m = fmaxf(m, g_pm[(bh*NCH + c)*48 + qi]);
    float num = 0.f, den = 0.f;
    #pragma unroll
    for (int c = 0; c < NCH; c++) {
        int base = (bh*NCH + c)*48 + qi;
        float w = __expf(g_pm[base] - m);
        den = fmaf(w, g_pl[base], den);
        num = fmaf(w, g_po[(size_t)base*HD + d], num);
    }
    g_ctx[(size_t)q*DMODEL + h*HD + d] = num / den;
}

// ============================================================================
// out projection: k-split (z), gate, atomicAdd into y
// ============================================================================
__global__ void __launch_bounds__(256) outproj_kernel(const float* __restrict__ W,
                                                      const float* __restrict__ bias,
                                                      float* __restrict__ y) {
    __shared__ float As[64*48];
    __shared__ float Bs[64*64];
    int tid = threadIdx.x;
    int tx = tid & 15, ty = tid >> 4;
    int cb = blockIdx.x * 64;
    int rt = blockIdx.y;
    int kb = blockIdx.z * 64;

    #pragma unroll
    for (int l = 0; l < 3; l++) {
        int fid = tid + l*256;
        int row = fid >> 4;
        int kc  = (fid & 15) << 2;
        float4 v = *(const float4*)&g_ctx[(size_t)(rt*48 + row)*DMODEL + kb + kc];
        As[(kc+0)*48 + row] = v.x; As[(kc+1)*48 + row] = v.y;
        As[(kc+2)*48 + row] = v.z; As[(kc+3)*48 + row] = v.w;
    }
    #pragma unroll
    for (int l = 0; l < 4; l++) {
        int fid = tid + l*256;
        int kr = fid >> 4;
        int c4 = (fid & 15) << 2;
        *(float4*)&Bs[kr*64 + c4] = *(const float4*)&W[(size_t)(kb + kr)*DMODEL + cb + c4];
    }
    __syncthreads();
    float acc[3][4];
    #pragma unroll
    for (int i = 0; i < 3; i++)
        #pragma unroll
        for (int j = 0; j < 4; j++) acc[i][j] = 0.f;
    #pragma unroll 8
    for (int k = 0; k < 64; k++) {
        float4 bv = *(const float4*)&Bs[k*64 + tx*4];
        #pragma unroll
        for (int i = 0; i < 3; i++) {
            float a = As[k*48 + ty*3 + i];
            acc[i][0] = fmaf(a, bv.x, acc[i][0]);
            acc[i][1] = fmaf(a, bv.y, acc[i][1]);
            acc[i][2] = fmaf(a, bv.z, acc[i][2]);
            acc[i][3] = fmaf(a, bv.w, acc[i][3]);
        }
    }
    #pragma unroll
    for (int i = 0; i < 3; i++) {
        int row = rt*48 + ty*3 + i;
        if (row < NQ) {
            int b = row / KSEL;
            int t = g_idx[row];
            float p = g_p1[b*SEQL + t];
            float* yr = y + (size_t)(b*SEQL + t)*DMODEL;
            #pragma unroll
            for (int j = 0; j < 4; j++) {
                int col = cb + tx*4 + j;
                float v = acc[i][j] + (blockIdx.z == 0 ? bias[col] : 0.f);
                atomicAdd(&yr[col], p * v);
            }
        }
    }
}

// ============================================================================
extern "C" void kernel_launch(void* const* d_in, const int* in_sizes, int n_in,
                              void* d_out, int out_size) {
    const float* x     = (const float*)d_in[0];
    const float* Wqkv  = (const float*)d_in[1];
    const float* bqkv  = (const float*)d_in[2];
    const float* sel_w = (const float*)d_in[3];
    const float* sel_b = (const float*)d_in[4];
    const float* out_w = (const float*)d_in[5];
    const float* out_b = (const float*)d_in[6];
    const float* temp  = (const float*)d_in[7];
    float* y = (float*)d_out;

    zero_kernel<<<NQP*DMODEL/1024, 256>>>();
    sel_copy_kernel<<<NROWS, 256>>>(x, sel_w, sel_b, temp, y);
    w_transpose_kernel<<<dim3(NKV/32, DMODEL/32), dim3(32, 8)>>>(Wqkv);
    kv_mma_kernel<<<dim3(NKV/128, NROWS/128), 256>>>(bqkv);
    ranksel_kernel<<<dim3(SEQL/64, BATCH), 256>>>();
    qproj_kernel<<<dim3(12, 2, 12), 256>>>(x, Wqkv, bqkv);
    attn_chunk_kernel<<<dim3(NCH, NH, BATCH), 256>>>();
    attn_combine_kernel<<<NQ*NH, HD>>>();
    outproj_kernel<<<dim3(12, 2, 12), 256>>>(out_w, out_b, y);
}

// round 9
// speedup vs baseline: 1.7929x; 1.0710x over previous
#include <cuda_runtime.h>
#include <cuda_bf16.h>
#include <math.h>
#include <stdint.h>

#define BATCH 2
#define SEQL  2048
#define DMODEL 768
#define NH    12
#define HD    64
#define KSEL  46
#define NKV   1536
#define NROWS (BATCH*SEQL)
#define WQKV_COLS 2304
#define NQ    (BATCH*KSEL)
#define NQP   96
#define CH    64
#define NCH   (SEQL/CH)

// -------- scratch --------
__device__ float g_p1[NROWS];
__device__ int   g_idx[NQ];
__device__ int   g_cnt[BATCH];
__device__ float g_kv[(size_t)NROWS * NKV];
__device__ float g_q[NQP*DMODEL];
__device__ float g_ctx[NQP*DMODEL];
__device__ float g_pm[BATCH*NH*NCH*48];
__device__ float g_pl[BATCH*NH*NCH*48];
__device__ float g_po[(size_t)BATCH*NH*NCH*48*HD];
__device__ __nv_bfloat16 g_xb[(size_t)NROWS * DMODEL];   // X bf16 [row][k]
__device__ __nv_bfloat16 g_wt[(size_t)NKV * DMODEL];     // W_kv bf16 [n][k]

__device__ __forceinline__ uint32_t smem_u32(const void* p) {
    uint32_t a;
    asm("{ .reg .u64 t; cvta.to.shared.u64 t, %1; cvt.u32.u64 %0, t; }" : "=r"(a) : "l"(p));
    return a;
}
__device__ __forceinline__ void ldm_x4(uint32_t* r, uint32_t addr) {
    asm volatile("ldmatrix.sync.aligned.m8n8.x4.shared.b16 {%0,%1,%2,%3}, [%4];"
        : "=r"(r[0]), "=r"(r[1]), "=r"(r[2]), "=r"(r[3]) : "r"(addr));
}
__device__ __forceinline__ void mma16816(float* c, const uint32_t* a, uint32_t b0, uint32_t b1) {
    asm volatile(
        "mma.sync.aligned.m16n8k16.row.col.f32.bf16.bf16.f32 "
        "{%0,%1,%2,%3}, {%4,%5,%6,%7}, {%8,%9}, {%0,%1,%2,%3};"
        : "+f"(c[0]), "+f"(c[1]), "+f"(c[2]), "+f"(c[3])
        : "r"(a[0]), "r"(a[1]), "r"(a[2]), "r"(a[3]), "r"(b0), "r"(b1));
}
#define CP_ASYNC16(dst, src) \
    asm volatile("cp.async.cg.shared.global [%0], [%1], 16;" :: "r"(dst), "l"(src))
#define CP_COMMIT() asm volatile("cp.async.commit_group;" ::: "memory")
#define CP_WAIT0()  asm volatile("cp.async.wait_group 0;" ::: "memory")

// ============================================================================
// zero g_q + reset slot counters
// ============================================================================
__global__ void zero_kernel() {
    int i = blockIdx.x * 256 + threadIdx.x;
    *(float4*)&g_q[i * 4] = make_float4(0.f, 0.f, 0.f, 0.f);
    if (i < BATCH) g_cnt[i] = 0;
}

// ============================================================================
// sel prob + y=x copy + x->bf16 convert (fused)
// ============================================================================
__global__ void sel_copy_kernel(const float* __restrict__ x,
                                const float* __restrict__ sel_w,
                                const float* __restrict__ sel_b,
                                const float* __restrict__ temp,
                                float* __restrict__ y) {
    int r = blockIdx.x;
    const float* xr = x + (size_t)r * DMODEL;
    float* yr = y + (size_t)r * DMODEL;
    __nv_bfloat16* xb = g_xb + (size_t)r * DMODEL;
    int tid = threadIdx.x;
    float p0 = 0.f, p1 = 0.f;
    #pragma unroll
    for (int j = tid; j < DMODEL; j += 256) {
        float v = xr[j];
        yr[j] = v;
        xb[j] = __float2bfloat16(v);
        float2 w = *(const float2*)&sel_w[2*j];
        p0 = fmaf(v, w.x, p0);
        p1 = fmaf(v, w.y, p1);
    }
    #pragma unroll
    for (int off = 16; off; off >>= 1) {
        p0 += __shfl_down_sync(0xffffffffu, p0, off);
        p1 += __shfl_down_sync(0xffffffffu, p1, off);
    }
    __shared__ float s0[8], s1[8];
    int w = tid >> 5;
    if ((tid & 31) == 0) { s0[w] = p0; s1[w] = p1; }
    __syncthreads();
    if (tid == 0) {
        float a0 = 0.f, a1 = 0.f;
        #pragma unroll
        for (int i = 0; i < 8; i++) { a0 += s0[i]; a1 += s1[i]; }
        a0 += sel_b[0]; a1 += sel_b[1];
        float d = (a1 - a0) / temp[0];
        g_p1[r] = 1.0f / (1.0f + expf(-d));
    }
}

// ============================================================================
// W_kv (cols 768:2304) -> g_wt[n][k] bf16 (transpose)
// ============================================================================
__global__ void w_transpose_kernel(const float* __restrict__ W) {
    __shared__ float t[32][33];
    int n0 = blockIdx.x * 32;
    int k0 = blockIdx.y * 32;
    int tx = threadIdx.x, ty = threadIdx.y;
    #pragma unroll
    for (int i = 0; i < 4; i++)
        t[ty + 8*i][tx] = W[(size_t)(k0 + ty + 8*i) * WQKV_COLS + 768 + n0 + tx];
    __syncthreads();
    #pragma unroll
    for (int i = 0; i < 4; i++)
        g_wt[(size_t)(n0 + ty + 8*i) * DMODEL + k0 + tx] = __float2bfloat16(t[tx][ty + 8*i]);
}

// ============================================================================
// KV GEMM: cp.async 2-stage + swizzled smem (conflict-free ldmatrix) + mma.sync.
// CTA 128x128, 8 warps (2M x 4N), K-chunk 32.
// SMEM layout: logical (r, u16B) -> byte (r>>1)*128 + ((((r&1)<<2)|u) ^ ((r>>1)&7))*16
// ============================================================================
#define STAGE_BYTES 8192   // 64 phys rows * 128 B

__global__ void __launch_bounds__(256) kv_mma_kernel(const float* __restrict__ bias) {
    __shared__ __align__(128) __nv_bfloat16 sA[2*4096];
    __shared__ __align__(128) __nv_bfloat16 sB[2*4096];
    int tid = threadIdx.x;
    int wid = tid >> 5, lane = tid & 31;
    int wm = wid & 1, wn = wid >> 1;
    int g = lane >> 2, tg = lane & 3;
    int row0 = blockIdx.y * 128;
    int col0 = blockIdx.x * 128;
    uint32_t baseA = smem_u32(sA), baseB = smem_u32(sB);

    // ---- cp.async loader: per stage each operand = 128 rows x 4 units(16B).
    // thread -> unit gu = tid&3, rows gr and gr+64 (gr = tid>>2). 2 ops x 2 rows.
    int gr = tid >> 2;
    int gu = tid & 3;
    int par = gr & 1;                  // same for gr+64
    int prow0 = gr >> 1;               // +32 for second row; &7 invariant
    int su = ((par << 2) | gu) ^ (prow0 & 7);
    uint32_t stA = baseA + (uint32_t)(prow0 * 128 + su * 16);
    uint32_t stB = baseB + (uint32_t)(prow0 * 128 + su * 16);
    const __nv_bfloat16* gA0 = g_xb + (size_t)(row0 + gr) * DMODEL + gu * 8;
    const __nv_bfloat16* gA1 = g_xb + (size_t)(row0 + gr + 64) * DMODEL + gu * 8;
    const __nv_bfloat16* gB0 = g_wt + (size_t)(col0 + gr) * DMODEL + gu * 8;
    const __nv_bfloat16* gB1 = g_wt + (size_t)(col0 + gr + 64) * DMODEL + gu * 8;

    // ---- ldmatrix lane constants
    int lrow = lane & 15, lsb = lane >> 4;
    int mrA = wm * 64 + lrow;
    int prA = mrA >> 1, paA = (mrA & 1) << 2, xa = prA & 7;
    int nrB = wn * 32 + lrow;
    int prB = nrB >> 1, paB = (nrB & 1) << 2, xb = prB & 7;

    float c[4][4][4];
    #pragma unroll
    for (int mi = 0; mi < 4; mi++)
        #pragma unroll
        for (int ni = 0; ni < 4; ni++)
            #pragma unroll
            for (int j = 0; j < 4; j++) c[mi][ni][j] = 0.f;

    // prologue: stage 0
    CP_ASYNC16(stA, gA0);                    CP_ASYNC16(stA + 32*128, gA1);
    CP_ASYNC16(stB, gB0);                    CP_ASYNC16(stB + 32*128, gB1);
    CP_COMMIT();

    for (int kc = 0; kc < 24; kc++) {
        CP_WAIT0();
        __syncthreads();
        if (kc < 23) {
            int k0 = (kc + 1) * 32;
            uint32_t so = (uint32_t)(((kc + 1) & 1) * STAGE_BYTES);
            CP_ASYNC16(stA + so, gA0 + k0);          CP_ASYNC16(stA + so + 32*128, gA1 + k0);
            CP_ASYNC16(stB + so, gB0 + k0);          CP_ASYNC16(stB + so + 32*128, gB1 + k0);
            CP_COMMIT();
        }
        uint32_t so = (uint32_t)((kc & 1) * STAGE_BYTES);
        #pragma unroll
        for (int ks = 0; ks < 2; ks++) {
            int u = ks * 2 + lsb;
            uint32_t offA = (uint32_t)(((paA | u) ^ xa) << 4);
            uint32_t offB = (uint32_t)(((paB | u) ^ xb) << 4);
            uint32_t A[4][4], Bf[2][4];
            #pragma unroll
            for (int mi = 0; mi < 4; mi++)
                ldm_x4(A[mi], baseA + so + (uint32_t)((prA + mi*8) * 128) + offA);
            #pragma unroll
            for (int bi = 0; bi < 2; bi++)
                ldm_x4(Bf[bi], baseB + so + (uint32_t)((prB + bi*8) * 128) + offB);
            #pragma unroll
            for (int mi = 0; mi < 4; mi++) {
                mma16816(c[mi][0], A[mi], Bf[0][0], Bf[0][2]);
                mma16816(c[mi][1], A[mi], Bf[0][1], Bf[0][3]);
                mma16816(c[mi][2], A[mi], Bf[1][0], Bf[1][2]);
                mma16816(c[mi][3], A[mi], Bf[1][1], Bf[1][3]);
            }
        }
    }

    #pragma unroll
    for (int mi = 0; mi < 4; mi++) {
        int row = row0 + wm * 64 + mi * 16;
        #pragma unroll
        for (int ni = 0; ni < 4; ni++) {
            int col = col0 + wn * 32 + ni * 8 + 2 * tg;
            float2 bb = *(const float2*)&bias[768 + col];
            float2 r0, r1;
            r0.x = c[mi][ni][0] + bb.x; r0.y = c[mi][ni][1] + bb.y;
            r1.x = c[mi][ni][2] + bb.x; r1.y = c[mi][ni][3] + bb.y;
            *(float2*)&g_kv[(size_t)(row + g) * NKV + col] = r0;
            *(float2*)&g_kv[(size_t)(row + g + 8) * NKV + col] = r1;
        }
    }
}

// ============================================================================
// rank-select top-KSEL (jax tie-break); slot order irrelevant downstream.
// ============================================================================
__global__ void __launch_bounds__(256) ranksel_kernel() {
    int b = blockIdx.y;
    __shared__ float vals[SEQL];
    int tid = threadIdx.x;
    int warp = tid >> 5, lane = tid & 31;
    #pragma unroll
    for (int l = 0; l < 8; l++) vals[tid + l * 256] = g_p1[b * SEQL + tid + l * 256];
    __syncthreads();
    #pragma unroll
    for (int i = 0; i < 8; i++) {
        int cand = blockIdx.x * 64 + warp * 8 + i;
        float v = vals[cand];
        int cnt = 0;
        #pragma unroll
        for (int l = 0; l < 64; l++) {
            int j = lane + l * 32;
            float u = vals[j];
            cnt += (u > v || (u == v && j < cand)) ? 1 : 0;
        }
        #pragma unroll
        for (int off = 16; off; off >>= 1)
            cnt += __shfl_xor_sync(0xffffffffu, cnt, off);
        if (lane == 0 && cnt < KSEL) {
            int slot = atomicAdd(&g_cnt[b], 1);
            g_idx[b * KSEL + slot] = cand;
        }
    }
}

// ============================================================================
// Q projection: gathered rows from x, k-split (z), atomicAdd into zeroed g_q.
// ============================================================================
__global__ void __launch_bounds__(256) qproj_kernel(const float* __restrict__ x,
                                                    const float* __restrict__ W,
                                                    const float* __restrict__ bias) {
    __shared__ float As[64*48];
    __shared__ float Bs[64*64];
    __shared__ int rowsrc[48];
    int tid = threadIdx.x;
    int tx = tid & 15, ty = tid >> 4;
    int cb = blockIdx.x * 64;
    int rt = blockIdx.y;
    int kb = blockIdx.z * 64;
    if (tid < 48) {
        int r = rt*48 + tid;
        rowsrc[tid] = (r < NQ) ? ((r / KSEL) * SEQL + g_idx[r]) : -1;
    }
    __syncthreads();

    #pragma unroll
    for (int l = 0; l < 3; l++) {
        int fid = tid + l*256;
        int row = fid >> 4;
        int kc  = (fid & 15) << 2;
        int src = rowsrc[row];
        float4 v = make_float4(0.f, 0.f, 0.f, 0.f);
        if (src >= 0) v = *(const float4*)&x[(size_t)src*DMODEL + kb + kc];
        As[(kc+0)*48 + row] = v.x; As[(kc+1)*48 + row] = v.y;
        As[(kc+2)*48 + row] = v.z; As[(kc+3)*48 + row] = v.w;
    }
    #pragma unroll
    for (int l = 0; l < 4; l++) {
        int fid = tid + l*256;
        int kr = fid >> 4;
        int c4 = (fid & 15) << 2;
        *(float4*)&Bs[kr*64 + c4] = *(const float4*)&W[(size_t)(kb + kr)*WQKV_COLS + cb + c4];
    }
    __syncthreads();
    float acc[3][4];
    #pragma unroll
    for (int i = 0; i < 3; i++)
        #pragma unroll
        for (int j = 0; j < 4; j++) acc[i][j] = 0.f;
    #pragma unroll 8
    for (int k = 0; k < 64; k++) {
        float4 bv = *(const float4*)&Bs[k*64 + tx*4];
        #pragma unroll
        for (int i = 0; i < 3; i++) {
            float a = As[k*48 + ty*3 + i];
            acc[i][0] = fmaf(a, bv.x, acc[i][0]);
            acc[i][1] = fmaf(a, bv.y, acc[i][1]);
            acc[i][2] = fmaf(a, bv.z, acc[i][2]);
            acc[i][3] = fmaf(a, bv.w, acc[i][3]);
        }
    }
    #pragma unroll
    for (int i = 0; i < 3; i++) {
        int row = rt*48 + ty*3 + i;
        if (row < NQ) {
            #pragma unroll
            for (int j = 0; j < 4; j++) {
                int col = cb + tx*4 + j;
                float v = acc[i][j] + (blockIdx.z == 0 ? bias[col] : 0.f);
                atomicAdd(&g_q[(size_t)row*DMODEL + col], v);
            }
        }
    }
}

// ============================================================================
// flash-decode attention chunk (fp32)
// ============================================================================
__global__ void __launch_bounds__(256) attn_chunk_kernel() {
    int c  = blockIdx.x;
    int h  = blockIdx.y;
    int b  = blockIdx.z;
    int c0 = c * CH;
    int tid = threadIdx.x;
    int tx = tid & 15, ty = tid >> 4;

    __shared__ float qs[48*HD];
    __shared__ float kv_s[CH*HD];
    __shared__ float S[48*66];
    __shared__ int   ts[48];

    if (tid < 48) ts[tid] = (tid < KSEL) ? g_idx[b*KSEL + tid] : -1;
    for (int idx = tid; idx < 48*HD; idx += 256) {
        int q = idx >> 6, d = idx & 63;
        qs[idx] = (q < KSEL) ? g_q[(size_t)(b*KSEL + q)*DMODEL + h*HD + d] * 0.125f : 0.f;
    }
    const float* kvb = g_kv + (size_t)b * SEQL * NKV;
    #pragma unroll
    for (int l = 0; l < 4; l++) {
        int fid = tid + l*256;
        int key = fid >> 4;
        int dq  = (fid & 15) << 2;
        float4 v = *(const float4*)&kvb[(size_t)(c0 + key)*NKV + h*HD + dq];
        kv_s[(dq+0)*CH + key] = v.x; kv_s[(dq+1)*CH + key] = v.y;
        kv_s[(dq+2)*CH + key] = v.z; kv_s[(dq+3)*CH + key] = v.w;
    }
    __syncthreads();

    float acc[3][4];
    #pragma unroll
    for (int i = 0; i < 3; i++)
        #pragma unroll
        for (int j = 0; j < 4; j++) acc[i][j] = 0.f;
    #pragma unroll 8
    for (int d = 0; d < HD; d++) {
        float4 bv = *(const float4*)&kv_s[d*CH + tx*4];
        #pragma unroll
        for (int i = 0; i < 3; i++) {
            float a = qs[(ty*3+i)*HD + d];
            acc[i][0] = fmaf(a, bv.x, acc[i][0]);
            acc[i][1] = fmaf(a, bv.y, acc[i][1]);
            acc[i][2] = fmaf(a, bv.z, acc[i][2]);
            acc[i][3] = fmaf(a, bv.w, acc[i][3]);
        }
    }
    #pragma unroll
    for (int i = 0; i < 3; i++) {
        int q = ty*3 + i;
        int tq = ts[q];
        #pragma unroll
        for (int j = 0; j < 4; j++) {
            int sg = c0 + tx*4 + j;
            S[q*66 + tx*4 + j] = (q < KSEL && sg <= tq) ? acc[i][j] : -1e30f;
        }
    }
    __syncthreads();

    #pragma unroll
    for (int l = 0; l < 4; l++) {
        int fid = tid + l*256;
        int key = fid >> 4;
        int dq  = (fid & 15) << 2;
        *(float4*)&kv_s[key*HD + dq] =
            *(const float4*)&kvb[(size_t)(c0 + key)*NKV + DMODEL + h*HD + dq];
    }
    if (tid < 48) {
        int q = tid;
        float m = -1e30f;
        #pragma unroll 8
        for (int k = 0; k < CH; k++) m = fmaxf(m, S[q*66 + k]);
        float l = 0.f;
        #pragma unroll 8
        for (int k = 0; k < CH; k++) {
            float v = S[q*66 + k];
            float p = (v > -1e29f) ? __expf(v - m) : 0.f;
            S[q*66 + k] = p;
            l += p;
        }
        int base = ((b*NH + h)*NCH + c)*48 + q;
        g_pm[base] = m;
        g_pl[base] = l;
    }
    __syncthreads();

    float acc2[3][4];
    #pragma unroll
    for (int i = 0; i < 3; i++)
        #pragma unroll
        for (int j = 0; j < 4; j++) acc2[i][j] = 0.f;
    #pragma unroll 8
    for (int k = 0; k < CH; k++) {
        float4 bv = *(const float4*)&kv_s[k*HD + tx*4];
        #pragma unroll
        for (int i = 0; i < 3; i++) {
            float a = S[(ty*3+i)*66 + k];
            acc2[i][0] = fmaf(a, bv.x, acc2[i][0]);
            acc2[i][1] = fmaf(a, bv.y, acc2[i][1]);
            acc2[i][2] = fmaf(a, bv.z, acc2[i][2]);
            acc2[i][3] = fmaf(a, bv.w, acc2[i][3]);
        }
    }
    size_t obase = ((size_t)((b*NH + h)*NCH + c))*48;
    #pragma unroll
    for (int i = 0; i < 3; i++) {
        float4 r; r.x = acc2[i][0]; r.y = acc2[i][1]; r.z = acc2[i][2]; r.w = acc2[i][3];
        *(float4*)&g_po[(obase + ty*3 + i)*HD + tx*4] = r;
    }
}

// ============================================================================
__global__ void attn_combine_kernel() {
    int bx = blockIdx.x;
    int q  = bx / NH;
    int h  = bx % NH;
    int b  = q / KSEL;
    int qi = q % KSEL;
    int d  = threadIdx.x;
    int bh = b*NH + h;

    float m = -1e30f;
    #pragma unroll
    for (int c = 0; c < NCH; c++)
        m = fmaxf(m, g_pm[(bh*NCH + c)*48 + qi]);
    float num = 0.f, den = 0.f;
    #pragma unroll
    for (int c = 0; c < NCH; c++) {
        int base = (bh*NCH + c)*48 + qi;
        float w = __expf(g_pm[base] - m);
        den = fmaf(w, g_pl[base], den);
        num = fmaf(w, g_po[(size_t)base*HD + d], num);
    }
    g_ctx[(size_t)q*DMODEL + h*HD + d] = num / den;
}

// ============================================================================
// out projection: k-split (z), gate, atomicAdd into y
// ============================================================================
__global__ void __launch_bounds__(256) outproj_kernel(const float* __restrict__ W,
                                                      const float* __restrict__ bias,
                                                      float* __restrict__ y) {
    __shared__ float As[64*48];
    __shared__ float Bs[64*64];
    int tid = threadIdx.x;
    int tx = tid & 15, ty = tid >> 4;
    int cb = blockIdx.x * 64;
    int rt = blockIdx.y;
    int kb = blockIdx.z * 64;

    #pragma unroll
    for (int l = 0; l < 3; l++) {
        int fid = tid + l*256;
        int row = fid >> 4;
        int kc  = (fid & 15) << 2;
        float4 v = *(const float4*)&g_ctx[(size_t)(rt*48 + row)*DMODEL + kb + kc];
        As[(kc+0)*48 + row] = v.x; As[(kc+1)*48 + row] = v.y;
        As[(kc+2)*48 + row] = v.z; As[(kc+3)*48 + row] = v.w;
    }
    #pragma unroll
    for (int l = 0; l < 4; l++) {
        int fid = tid + l*256;
        int kr = fid >> 4;
        int c4 = (fid & 15) << 2;
        *(float4*)&Bs[kr*64 + c4] = *(const float4*)&W[(size_t)(kb + kr)*DMODEL + cb + c4];
    }
    __syncthreads();
    float acc[3][4];
    #pragma unroll
    for (int i = 0; i < 3; i++)
        #pragma unroll
        for (int j = 0; j < 4; j++) acc[i][j] = 0.f;
    #pragma unroll 8
    for (int k = 0; k < 64; k++) {
        float4 bv = *(const float4*)&Bs[k*64 + tx*4];
        #pragma unroll
        for (int i = 0; i < 3; i++) {
            float a = As[k*48 + ty*3 + i];
            acc[i][0] = fmaf(a, bv.x, acc[i][0]);
            acc[i][1] = fmaf(a, bv.y, acc[i][1]);
            acc[i][2] = fmaf(a, bv.z, acc[i][2]);
            acc[i][3] = fmaf(a, bv.w, acc[i][3]);
        }
    }
    #pragma unroll
    for (int i = 0; i < 3; i++) {
        int row = rt*48 + ty*3 + i;
        if (row < NQ) {
            int b = row / KSEL;
            int t = g_idx[row];
            float p = g_p1[b*SEQL + t];
            float* yr = y + (size_t)(b*SEQL + t)*DMODEL;
            #pragma unroll
            for (int j = 0; j < 4; j++) {
                int col = cb + tx*4 + j;
                float v = acc[i][j] + (blockIdx.z == 0 ? bias[col] : 0.f);
                atomicAdd(&yr[col], p * v);
            }
        }
    }
}

// ============================================================================
extern "C" void kernel_launch(void* const* d_in, const int* in_sizes, int n_in,
                              void* d_out, int out_size) {
    const float* x     = (const float*)d_in[0];
    const float* Wqkv  = (const float*)d_in[1];
    const float* bqkv  = (const float*)d_in[2];
    const float* sel_w = (const float*)d_in[3];
    const float* sel_b = (const float*)d_in[4];
    const float* out_w = (const float*)d_in[5];
    const float* out_b = (const float*)d_in[6];
    const float* temp  = (const float*)d_in[7];
    float* y = (float*)d_out;

    zero_kernel<<<NQP*DMODEL/1024, 256>>>();
    sel_copy_kernel<<<NROWS, 256>>>(x, sel_w, sel_b, temp, y);
    w_transpose_kernel<<<dim3(NKV/32, DMODEL/32), dim3(32, 8)>>>(Wqkv);
    kv_mma_kernel<<<dim3(NKV/128, NROWS/128), 256>>>(bqkv);
    ranksel_kernel<<<dim3(SEQL/64, BATCH), 256>>>();
    qproj_kernel<<<dim3(12, 2, 12), 256>>>(x, Wqkv, bqkv);
    attn_chunk_kernel<<<dim3(NCH, NH, BATCH), 256>>>();
    attn_combine_kernel<<<NQ*NH, HD>>>();
    outproj_kernel<<<dim3(12, 2, 12), 256>>>(out_w, out_b, y);
}